// round 1
// baseline (speedup 1.0000x reference)
#include <cuda_runtime.h>
#include <cstddef>

#define NN 50000
#define HD 64

// ---- scratch (device globals; no allocations allowed) ----
__device__ __align__(256) float g_h[NN * HD];     // xp (layer input / output)
__device__ __align__(256) float g_hn[NN * HD];    // h = xp @ W
__device__ __align__(256) float g_out[NN * HD];   // aggregation output
__device__ float g_asn[NN];
__device__ float g_adn[NN];
__device__ float g_denom[NN];
__device__ float g_winv[NN];
__device__ float g_pool[64 * 32];                 // padded: channel c at c*32 (spread LTS partitions)

__device__ __forceinline__ float lrelu(float x) { return x > 0.f ? x : 0.2f * x; }

// ============================================================================
// K1: h = xp @ W  (+ fused attention scalars as_n, ad_n, and self-loop denom init)
// Warp handles NPW nodes; lane l computes channels l and l+32 (conflict-free smem).
// ============================================================================
template <int KDIM, int NPW>
__global__ void gemm_attn_kernel(const float* __restrict__ xp,
                                 const float* __restrict__ W,
                                 const float* __restrict__ a_s,
                                 const float* __restrict__ a_d,
                                 int zero_pool) {
    __shared__ float Ws[KDIM * 64];
    __shared__ float xs[8][NPW][KDIM];
    int tid = threadIdx.x;
    for (int i = tid; i < KDIM * 64; i += 256) Ws[i] = W[i];
    if (zero_pool && blockIdx.x == 0 && tid < 64) g_pool[tid * 32] = 0.f;
    __syncthreads();

    int warp = tid >> 5, lane = tid & 31;
    int nbase = (blockIdx.x * 8 + warp) * NPW;
    const float* src = xp ? xp : g_h;

    #pragma unroll
    for (int j = 0; j < NPW; j++) {
        int n = nbase + j;
        if (n < NN) {
            #pragma unroll
            for (int k = lane; k < KDIM; k += 32)
                xs[warp][j][k] = src[(size_t)n * KDIM + k];
        }
    }
    __syncwarp();

    float acc0[NPW], acc1[NPW];
    #pragma unroll
    for (int j = 0; j < NPW; j++) { acc0[j] = 0.f; acc1[j] = 0.f; }

    float asl0 = a_s[lane], asl1 = a_s[lane + 32];
    float adl0 = a_d[lane], adl1 = a_d[lane + 32];

    #pragma unroll 4
    for (int k = 0; k < KDIM; k++) {
        float w0 = Ws[k * 64 + lane];
        float w1 = Ws[k * 64 + lane + 32];
        #pragma unroll
        for (int j = 0; j < NPW; j++) {
            float xv = xs[warp][j][k];
            acc0[j] = fmaf(xv, w0, acc0[j]);
            acc1[j] = fmaf(xv, w1, acc1[j]);
        }
    }

    #pragma unroll
    for (int j = 0; j < NPW; j++) {
        int n = nbase + j;
        if (n >= NN) break;
        g_hn[(size_t)n * 64 + lane]      = acc0[j];
        g_hn[(size_t)n * 64 + lane + 32] = acc1[j];
        float s = acc0[j] * asl0 + acc1[j] * asl1;
        float d = acc0[j] * adl0 + acc1[j] * adl1;
        #pragma unroll
        for (int o = 16; o > 0; o >>= 1) {
            s += __shfl_xor_sync(0xffffffffu, s, o);
            d += __shfl_xor_sync(0xffffffffu, d, o);
        }
        if (lane == 0) {
            g_asn[n] = s;
            g_adn[n] = d;
            g_denom[n] = __expf(lrelu(s + d));   // self-loop term
        }
    }
}

// ============================================================================
// K2: denom[dst] += exp(lrelu(as[src] + ad[dst]))   (1 thread / edge)
// ============================================================================
__global__ void edge_denom_kernel(const int* __restrict__ ei, int E) {
    int j = blockIdx.x * blockDim.x + threadIdx.x;
    if (j >= E) return;
    int src = ei[j];
    int dst = ei[E + j];
    float ex = __expf(lrelu(g_asn[src] + g_adn[dst]));
    atomicAdd(&g_denom[dst], ex);
}

// ============================================================================
// K3: winv = 1/(denom+eps);  out[i][:] = selfw * h[i][:]
// ============================================================================
__global__ void node_init_kernel() {
    int t = blockIdx.x * blockDim.x + threadIdx.x;
    int node = t >> 6, c = t & 63;
    if (node >= NN) return;
    float wi = 1.f / (g_denom[node] + 1e-16f);
    float selfw = __expf(lrelu(g_asn[node] + g_adn[node])) * wi;
    if (c == 0) g_winv[node] = wi;
    g_out[(size_t)node * 64 + c] = selfw * g_hn[(size_t)node * 64 + c];
}

// ============================================================================
// K4: out[dst] += alpha * h[src]   (16 lanes/edge, red.global.add.v4.f32)
// ============================================================================
__global__ void edge_scatter_kernel(const int* __restrict__ ei, int E) {
    int t = blockIdx.x * blockDim.x + threadIdx.x;
    int j = t >> 4, l = t & 15;
    if (j >= E) return;
    int src = ei[j];
    int dst = ei[E + j];
    float w = __expf(lrelu(g_asn[src] + g_adn[dst])) * g_winv[dst];
    float4 v = *(const float4*)(g_hn + (size_t)src * 64 + l * 4);
    v.x *= w; v.y *= w; v.z *= w; v.w *= w;
    float* a = g_out + (size_t)dst * 64 + l * 4;
    asm volatile("red.global.add.v4.f32 [%0], {%1,%2,%3,%4};"
                 :: "l"(a), "f"(v.x), "f"(v.y), "f"(v.z), "f"(v.w) : "memory");
}

// ============================================================================
// K5: xnew = bn(relu(out + bias)) [+ xp @ projW + projb] ; optional mean-pool accum
// ============================================================================
__global__ void post_kernel(const float* __restrict__ bias,
                            const float* __restrict__ bng, const float* __restrict__ bnb,
                            const float* __restrict__ bnm, const float* __restrict__ bnv,
                            const float* __restrict__ projW, const float* __restrict__ projb,
                            int do_pool) {
    __shared__ float Ws[64 * 64];
    __shared__ float xs[8][4][64];
    __shared__ float bsum[64];
    int tid = threadIdx.x;
    bool has_proj = (projW != nullptr);
    if (has_proj)
        for (int i = tid; i < 4096; i += 256) Ws[i] = projW[i];
    if (tid < 64) bsum[tid] = 0.f;
    __syncthreads();

    int warp = tid >> 5, lane = tid & 31;
    int nbase = (blockIdx.x * 8 + warp) * 4;

    if (has_proj) {
        #pragma unroll
        for (int j = 0; j < 4; j++) {
            int n = nbase + j;
            if (n < NN) {
                xs[warp][j][lane]      = g_h[(size_t)n * 64 + lane];
                xs[warp][j][lane + 32] = g_h[(size_t)n * 64 + lane + 32];
            }
        }
        __syncwarp();
    }

    float b0 = bias[lane], b1 = bias[lane + 32];
    float sc0 = bng[lane] * rsqrtf(bnv[lane] + 1e-5f);
    float sc1 = bng[lane + 32] * rsqrtf(bnv[lane + 32] + 1e-5f);
    float sh0 = bnb[lane] - bnm[lane] * sc0;
    float sh1 = bnb[lane + 32] - bnm[lane + 32] * sc1;
    float pb0 = has_proj ? projb[lane] : 0.f;
    float pb1 = has_proj ? projb[lane + 32] : 0.f;

    #pragma unroll
    for (int j = 0; j < 4; j++) {
        int n = nbase + j;
        if (n < NN) {
            float p0 = pb0, p1 = pb1;
            if (has_proj) {
                #pragma unroll 4
                for (int k = 0; k < 64; k++) {
                    float xv = xs[warp][j][k];
                    p0 = fmaf(xv, Ws[k * 64 + lane], p0);
                    p1 = fmaf(xv, Ws[k * 64 + lane + 32], p1);
                }
            }
            float o0 = g_out[(size_t)n * 64 + lane] + b0;
            float o1 = g_out[(size_t)n * 64 + lane + 32] + b1;
            o0 = o0 > 0.f ? o0 : 0.f;
            o1 = o1 > 0.f ? o1 : 0.f;
            float y0 = o0 * sc0 + sh0 + p0;
            float y1 = o1 * sc1 + sh1 + p1;
            g_h[(size_t)n * 64 + lane]      = y0;
            g_h[(size_t)n * 64 + lane + 32] = y1;
            if (do_pool) {
                atomicAdd(&bsum[lane], y0);
                atomicAdd(&bsum[lane + 32], y1);
            }
        }
    }
    if (do_pool) {
        __syncthreads();
        if (tid < 64) atomicAdd(&g_pool[tid * 32], bsum[tid]);
    }
}

// ============================================================================
// Head: g = pool/N; h1 = bn(relu(g@hW1+hb1)); out = h1@hW2 + hb2
// ============================================================================
__global__ void head_kernel(const float* __restrict__ hW1, const float* __restrict__ hb1,
                            const float* __restrict__ hg, const float* __restrict__ hbb,
                            const float* __restrict__ hm, const float* __restrict__ hv,
                            const float* __restrict__ hW2, const float* __restrict__ hb2,
                            float* __restrict__ out) {
    __shared__ float gsh[64];
    __shared__ float h1[32];
    int t = threadIdx.x;
    if (t < 64) gsh[t] = g_pool[t * 32] * (1.f / (float)NN);
    __syncthreads();
    if (t < 32) {
        float acc = hb1[t];
        #pragma unroll 8
        for (int k = 0; k < 64; k++) acc = fmaf(gsh[k], hW1[k * 32 + t], acc);
        acc = acc > 0.f ? acc : 0.f;
        float sc = hg[t] * rsqrtf(hv[t] + 1e-5f);
        h1[t] = (acc - hm[t]) * sc + hbb[t];
    }
    __syncthreads();
    if (t == 0) {
        float acc = hb2[0];
        #pragma unroll
        for (int j = 0; j < 32; j++) acc = fmaf(h1[j], hW2[j], acc);
        out[0] = acc;
    }
}

// ============================================================================
extern "C" void kernel_launch(void* const* d_in, const int* in_sizes, int n_in,
                              void* d_out, int out_size) {
    const float* x        = (const float*)d_in[0];
    const int*   ei       = (const int*)d_in[1];
    const float* conv1_W  = (const float*)d_in[2];
    const float* conv1_as = (const float*)d_in[3];
    const float* conv1_ad = (const float*)d_in[4];
    const float* conv1_b  = (const float*)d_in[5];
    const float* convW    = (const float*)d_in[6];
    const float* conv_as  = (const float*)d_in[7];
    const float* conv_ad  = (const float*)d_in[8];
    const float* conv_b   = (const float*)d_in[9];
    const float* bn_g     = (const float*)d_in[10];
    const float* bn_b     = (const float*)d_in[11];
    const float* bn_m     = (const float*)d_in[12];
    const float* bn_v     = (const float*)d_in[13];
    const float* projW    = (const float*)d_in[14];
    const float* projb    = (const float*)d_in[15];
    const float* hW1      = (const float*)d_in[16];
    const float* hb1      = (const float*)d_in[17];
    const float* hbn_g    = (const float*)d_in[18];
    const float* hbn_b    = (const float*)d_in[19];
    const float* hbn_m    = (const float*)d_in[20];
    const float* hbn_v    = (const float*)d_in[21];
    const float* hW2      = (const float*)d_in[22];
    const float* hb2      = (const float*)d_in[23];

    int E = in_sizes[1] / 2;

    const int gemm128_blocks = (NN + 15) / 16;   // NPW=2, 8 warps -> 16 nodes/block
    const int gemm64_blocks  = (NN + 31) / 32;   // NPW=4 -> 32 nodes/block
    const int edge_blocks    = (E + 255) / 256;
    const int node_blocks    = (NN * 64 + 255) / 256;
    const int scat_blocks    = (E * 16 + 255) / 256;
    const int post_blocks    = (NN + 31) / 32;

    // ---- layer 1 (IN=128) ----
    gemm_attn_kernel<128, 2><<<gemm128_blocks, 256>>>(x, conv1_W, conv1_as, conv1_ad, 1);
    edge_denom_kernel<<<edge_blocks, 256>>>(ei, E);
    node_init_kernel<<<node_blocks, 256>>>();
    edge_scatter_kernel<<<scat_blocks, 256>>>(ei, E);
    post_kernel<<<post_blocks, 256>>>(conv1_b, bn_g, bn_b, bn_m, bn_v,
                                      nullptr, nullptr, 0);

    // ---- layers 2..5 ----
    for (int l = 0; l < 4; l++) {
        gemm_attn_kernel<64, 4><<<gemm64_blocks, 256>>>(nullptr, convW + l * 4096,
                                                        conv_as + l * 64, conv_ad + l * 64, 0);
        edge_denom_kernel<<<edge_blocks, 256>>>(ei, E);
        node_init_kernel<<<node_blocks, 256>>>();
        edge_scatter_kernel<<<scat_blocks, 256>>>(ei, E);
        post_kernel<<<post_blocks, 256>>>(conv_b + l * 64,
                                          bn_g + (l + 1) * 64, bn_b + (l + 1) * 64,
                                          bn_m + (l + 1) * 64, bn_v + (l + 1) * 64,
                                          projW + l * 4096, projb + l * 64,
                                          (l == 3) ? 1 : 0);
    }

    // ---- head ----
    head_kernel<<<1, 64>>>(hW1, hb1, hbn_g, hbn_b, hbn_m, hbn_v, hW2, hb2, (float*)d_out);
}

// round 2
// speedup vs baseline: 1.1657x; 1.1657x over previous
#include <cuda_runtime.h>
#include <cstddef>

#define NN 50000
#define HD 64
#define EMAX 800000

// ---- scratch (device globals) ----
__device__ __align__(256) float g_h[NN * HD];     // xp (layer input / output)
__device__ __align__(256) float g_hn[NN * HD];    // h = xp @ W
__device__ float g_asn[NN];
__device__ float g_adn[NN];
__device__ float g_pool[64 * 32];                 // padded: channel c at c*32
__device__ int   g_cnt[NN];
__device__ int   g_off[NN + 1];
__device__ int   g_cur[NN];
__device__ int   g_srcs[EMAX];

__device__ __forceinline__ float lrelu(float x) { return x > 0.f ? x : 0.2f * x; }

// ============================================================================
// Sort phase (once per launch): CSR by dst
// ============================================================================
__global__ void zero_kernel() {
    int i = blockIdx.x * blockDim.x + threadIdx.x;
    if (i < NN) g_cnt[i] = 0;
    if (blockIdx.x == 0 && threadIdx.x < 64) g_pool[threadIdx.x * 32] = 0.f;
}

__global__ void hist_kernel(const int* __restrict__ ei, int E) {
    int j = blockIdx.x * blockDim.x + threadIdx.x;
    if (j >= E) return;
    atomicAdd(&g_cnt[ei[E + j]], 1);
}

__global__ void scan_kernel() {   // single block, 1024 threads
    __shared__ int wsum[32];
    __shared__ int sbase;
    int tid = threadIdx.x, lane = tid & 31, warp = tid >> 5;
    if (tid == 0) sbase = 0;
    __syncthreads();
    for (int base = 0; base < NN; base += 1024) {
        int i = base + tid;
        int c = (i < NN) ? g_cnt[i] : 0;
        int v = c;
        #pragma unroll
        for (int o = 1; o < 32; o <<= 1) {
            int t = __shfl_up_sync(0xffffffffu, v, o);
            if (lane >= o) v += t;
        }
        if (lane == 31) wsum[warp] = v;
        __syncthreads();
        if (warp == 0) {
            int w = wsum[lane];
            #pragma unroll
            for (int o = 1; o < 32; o <<= 1) {
                int t = __shfl_up_sync(0xffffffffu, w, o);
                if (lane >= o) w += t;
            }
            wsum[lane] = w;
        }
        __syncthreads();
        int warpoff = warp ? wsum[warp - 1] : 0;
        int total = wsum[31];
        int excl = sbase + warpoff + v - c;
        if (i < NN) { g_off[i] = excl; g_cur[i] = excl; }
        __syncthreads();
        if (tid == 0) sbase += total;
        __syncthreads();
    }
    if (threadIdx.x == 0) g_off[NN] = sbase;
}

__global__ void sortedge_kernel(const int* __restrict__ ei, int E) {
    int j = blockIdx.x * blockDim.x + threadIdx.x;
    if (j >= E) return;
    int src = ei[j];
    int dst = ei[E + j];
    int pos = atomicAdd(&g_cur[dst], 1);
    if (pos < EMAX) g_srcs[pos] = src;
}

// ============================================================================
// K1: h = xp @ W  (+ attention scalars as_n, ad_n). Warp: NPW nodes x GROUPS.
// ============================================================================
template <int KDIM, int NPW, int GROUPS>
__global__ void gemm_attn_kernel(const float* __restrict__ xp,
                                 const float* __restrict__ W,
                                 const float* __restrict__ a_s,
                                 const float* __restrict__ a_d) {
    __shared__ float Ws[KDIM * 64];
    __shared__ float xs[8][NPW][KDIM];
    int tid = threadIdx.x;
    for (int i = tid; i < KDIM * 64; i += 256) Ws[i] = W[i];
    __syncthreads();

    int warp = tid >> 5, lane = tid & 31;
    const float* src = xp ? xp : g_h;
    float asl0 = a_s[lane], asl1 = a_s[lane + 32];
    float adl0 = a_d[lane], adl1 = a_d[lane + 32];

    for (int g = 0; g < GROUPS; g++) {
        int nbase = ((blockIdx.x * 8 + warp) * GROUPS + g) * NPW;
        if (nbase >= NN) break;
        #pragma unroll
        for (int j = 0; j < NPW; j++) {
            int n = nbase + j;
            if (n < NN) {
                #pragma unroll
                for (int k = lane; k < KDIM; k += 32)
                    xs[warp][j][k] = src[(size_t)n * KDIM + k];
            }
        }
        __syncwarp();

        float acc0[NPW], acc1[NPW];
        #pragma unroll
        for (int j = 0; j < NPW; j++) { acc0[j] = 0.f; acc1[j] = 0.f; }

        #pragma unroll 4
        for (int k = 0; k < KDIM; k++) {
            float w0 = Ws[k * 64 + lane];
            float w1 = Ws[k * 64 + lane + 32];
            #pragma unroll
            for (int j = 0; j < NPW; j++) {
                float xv = xs[warp][j][k];
                acc0[j] = fmaf(xv, w0, acc0[j]);
                acc1[j] = fmaf(xv, w1, acc1[j]);
            }
        }

        #pragma unroll
        for (int j = 0; j < NPW; j++) {
            int n = nbase + j;
            if (n >= NN) break;
            g_hn[(size_t)n * 64 + lane]      = acc0[j];
            g_hn[(size_t)n * 64 + lane + 32] = acc1[j];
            float s = acc0[j] * asl0 + acc1[j] * asl1;
            float d = acc0[j] * adl0 + acc1[j] * adl1;
            #pragma unroll
            for (int o = 16; o > 0; o >>= 1) {
                s += __shfl_xor_sync(0xffffffffu, s, o);
                d += __shfl_xor_sync(0xffffffffu, d, o);
            }
            if (lane == 0) { g_asn[n] = s; g_adn[n] = d; }
        }
        __syncwarp();
    }
}

// ============================================================================
// K2 (fused): per-dst gather-aggregate + softmax-normalize + bias/relu/BN
//             [+ proj residual] [+ mean-pool accum]. One warp per node, 8 nodes/warp.
// ============================================================================
template <bool HAS_PROJ, bool DO_POOL>
__global__ void aggregate_kernel(const float* __restrict__ bias,
                                 const float* __restrict__ bng, const float* __restrict__ bnb,
                                 const float* __restrict__ bnm, const float* __restrict__ bnv,
                                 const float* __restrict__ projW, const float* __restrict__ projb) {
    __shared__ float Ws[HAS_PROJ ? 4096 : 64];
    __shared__ float bsum[64];
    int tid = threadIdx.x;
    if (HAS_PROJ)
        for (int i = tid; i < 4096; i += 256) Ws[i] = projW[i];
    if (DO_POOL && tid < 64) bsum[tid] = 0.f;
    __syncthreads();

    int warp = tid >> 5, lane = tid & 31;
    float b0 = bias[lane], b1 = bias[lane + 32];
    float sc0 = bng[lane] * rsqrtf(bnv[lane] + 1e-5f);
    float sc1 = bng[lane + 32] * rsqrtf(bnv[lane + 32] + 1e-5f);
    float sh0 = bnb[lane] - bnm[lane] * sc0;
    float sh1 = bnb[lane + 32] - bnm[lane + 32] * sc1;
    float pb0 = HAS_PROJ ? projb[lane] : 0.f;
    float pb1 = HAS_PROJ ? projb[lane + 32] : 0.f;

    #pragma unroll 1
    for (int g = 0; g < 8; g++) {
        int n = (blockIdx.x * 8 + warp) * 8 + g;
        if (n >= NN) break;
        int start = g_off[n], end = g_off[n + 1];
        float adn_n = g_adn[n];
        float wself = __expf(lrelu(g_asn[n] + adn_n));
        const float* hn_n = g_hn + (size_t)n * 64;
        float acc0 = wself * hn_n[lane];
        float acc1 = wself * hn_n[lane + 32];
        float denom = wself;

        #pragma unroll 4
        for (int e = start; e < end; e++) {
            int src = __ldg(&g_srcs[e]);
            float w = __expf(lrelu(g_asn[src] + adn_n));
            denom += w;
            const float* hs = g_hn + (size_t)src * 64;
            acc0 = fmaf(w, hs[lane], acc0);
            acc1 = fmaf(w, hs[lane + 32], acc1);
        }

        float inv = 1.f / (denom + 1e-16f);
        float o0 = acc0 * inv + b0;
        float o1 = acc1 * inv + b1;
        o0 = o0 > 0.f ? o0 : 0.f;
        o1 = o1 > 0.f ? o1 : 0.f;
        float y0 = o0 * sc0 + sh0;
        float y1 = o1 * sc1 + sh1;

        if (HAS_PROJ) {
            float x0 = g_h[(size_t)n * 64 + lane];
            float x1 = g_h[(size_t)n * 64 + lane + 32];
            float p0 = pb0, p1 = pb1;
            #pragma unroll 8
            for (int k = 0; k < 32; k++) {
                float xv = __shfl_sync(0xffffffffu, x0, k);
                p0 = fmaf(xv, Ws[k * 64 + lane], p0);
                p1 = fmaf(xv, Ws[k * 64 + lane + 32], p1);
            }
            #pragma unroll 8
            for (int k = 0; k < 32; k++) {
                float xv = __shfl_sync(0xffffffffu, x1, k);
                p0 = fmaf(xv, Ws[(k + 32) * 64 + lane], p0);
                p1 = fmaf(xv, Ws[(k + 32) * 64 + lane + 32], p1);
            }
            y0 += p0; y1 += p1;
        }

        g_h[(size_t)n * 64 + lane]      = y0;
        g_h[(size_t)n * 64 + lane + 32] = y1;
        if (DO_POOL) {
            atomicAdd(&bsum[lane], y0);
            atomicAdd(&bsum[lane + 32], y1);
        }
    }
    if (DO_POOL) {
        __syncthreads();
        if (tid < 64) atomicAdd(&g_pool[tid * 32], bsum[tid]);
    }
}

// ============================================================================
// Head: g = pool/N; h1 = bn(relu(g@hW1+hb1)); out = h1@hW2 + hb2
// ============================================================================
__global__ void head_kernel(const float* __restrict__ hW1, const float* __restrict__ hb1,
                            const float* __restrict__ hg, const float* __restrict__ hbb,
                            const float* __restrict__ hm, const float* __restrict__ hv,
                            const float* __restrict__ hW2, const float* __restrict__ hb2,
                            float* __restrict__ out) {
    __shared__ float gsh[64];
    __shared__ float h1[32];
    int t = threadIdx.x;
    if (t < 64) gsh[t] = g_pool[t * 32] * (1.f / (float)NN);
    __syncthreads();
    if (t < 32) {
        float acc = hb1[t];
        #pragma unroll 8
        for (int k = 0; k < 64; k++) acc = fmaf(gsh[k], hW1[k * 32 + t], acc);
        acc = acc > 0.f ? acc : 0.f;
        float sc = hg[t] * rsqrtf(hv[t] + 1e-5f);
        h1[t] = (acc - hm[t]) * sc + hbb[t];
    }
    __syncthreads();
    if (t == 0) {
        float acc = hb2[0];
        #pragma unroll
        for (int j = 0; j < 32; j++) acc = fmaf(h1[j], hW2[j], acc);
        out[0] = acc;
    }
}

// ============================================================================
extern "C" void kernel_launch(void* const* d_in, const int* in_sizes, int n_in,
                              void* d_out, int out_size) {
    const float* x        = (const float*)d_in[0];
    const int*   ei       = (const int*)d_in[1];
    const float* conv1_W  = (const float*)d_in[2];
    const float* conv1_as = (const float*)d_in[3];
    const float* conv1_ad = (const float*)d_in[4];
    const float* conv1_b  = (const float*)d_in[5];
    const float* convW    = (const float*)d_in[6];
    const float* conv_as  = (const float*)d_in[7];
    const float* conv_ad  = (const float*)d_in[8];
    const float* conv_b   = (const float*)d_in[9];
    const float* bn_g     = (const float*)d_in[10];
    const float* bn_b     = (const float*)d_in[11];
    const float* bn_m     = (const float*)d_in[12];
    const float* bn_v     = (const float*)d_in[13];
    const float* projW    = (const float*)d_in[14];
    const float* projb    = (const float*)d_in[15];
    const float* hW1      = (const float*)d_in[16];
    const float* hb1      = (const float*)d_in[17];
    const float* hbn_g    = (const float*)d_in[18];
    const float* hbn_b    = (const float*)d_in[19];
    const float* hbn_m    = (const float*)d_in[20];
    const float* hbn_v    = (const float*)d_in[21];
    const float* hW2      = (const float*)d_in[22];
    const float* hb2      = (const float*)d_in[23];

    int E = in_sizes[1] / 2;

    const int edge_blocks = (E + 255) / 256;
    const int agg_blocks  = (NN + 63) / 64;    // 8 warps x 8 nodes
    const int g128_blocks = (NN + 127) / 128;  // NPW=2, GROUPS=8
    const int g64_blocks  = (NN + 127) / 128;  // NPW=4, GROUPS=4

    // ---- build CSR (edges identical for all layers) ----
    zero_kernel<<<(NN + 255) / 256, 256>>>();
    hist_kernel<<<edge_blocks, 256>>>(ei, E);
    scan_kernel<<<1, 1024>>>();
    sortedge_kernel<<<edge_blocks, 256>>>(ei, E);

    // ---- layer 1 (IN=128, no proj) ----
    gemm_attn_kernel<128, 2, 8><<<g128_blocks, 256>>>(x, conv1_W, conv1_as, conv1_ad);
    aggregate_kernel<false, false><<<agg_blocks, 256>>>(conv1_b, bn_g, bn_b, bn_m, bn_v,
                                                        nullptr, nullptr);

    // ---- layers 2..5 ----
    for (int l = 0; l < 4; l++) {
        gemm_attn_kernel<64, 4, 4><<<g64_blocks, 256>>>(nullptr, convW + l * 4096,
                                                        conv_as + l * 64, conv_ad + l * 64);
        if (l == 3)
            aggregate_kernel<true, true><<<agg_blocks, 256>>>(conv_b + l * 64,
                bn_g + (l + 1) * 64, bn_b + (l + 1) * 64, bn_m + (l + 1) * 64, bn_v + (l + 1) * 64,
                projW + l * 4096, projb + l * 64);
        else
            aggregate_kernel<true, false><<<agg_blocks, 256>>>(conv_b + l * 64,
                bn_g + (l + 1) * 64, bn_b + (l + 1) * 64, bn_m + (l + 1) * 64, bn_v + (l + 1) * 64,
                projW + l * 4096, projb + l * 64);
    }

    // ---- head ----
    head_kernel<<<1, 64>>>(hW1, hb1, hbn_g, hbn_b, hbn_m, hbn_v, hW2, hb2, (float*)d_out);
}

// round 3
// speedup vs baseline: 1.1736x; 1.0067x over previous
#include <cuda_runtime.h>
#include <cstddef>

#define NN 50000
#define HD 64
#define EMAX 800000
#define FULLMASK 0xffffffffu

// ---- scratch (device globals) ----
__device__ __align__(256) float g_h[NN * HD];     // xp (layer input / output)
__device__ __align__(256) float g_hn[NN * HD];    // h = xp @ W
__device__ float g_asn[NN];
__device__ float g_adn[NN];
__device__ float g_pool[64 * 32];                 // padded: channel c at c*32
__device__ int   g_cnt[NN];
__device__ int   g_off[NN + 1];
__device__ int   g_cur[NN];
__device__ int   g_srcs[EMAX];

__device__ __forceinline__ float lrelu(float x) { return x > 0.f ? x : 0.2f * x; }

// ============================================================================
// Sort phase (once per launch): CSR by dst
// ============================================================================
__global__ void zero_kernel() {
    int i = blockIdx.x * blockDim.x + threadIdx.x;
    if (i < NN) g_cnt[i] = 0;
    if (blockIdx.x == 0 && threadIdx.x < 64) g_pool[threadIdx.x * 32] = 0.f;
}

__global__ void hist_kernel(const int* __restrict__ ei, int E) {
    int j = blockIdx.x * blockDim.x + threadIdx.x;
    if (j >= E) return;
    atomicAdd(&g_cnt[ei[E + j]], 1);
}

__global__ void scan_kernel() {   // single block, 1024 threads
    __shared__ int wsum[32];
    __shared__ int sbase;
    int tid = threadIdx.x, lane = tid & 31, warp = tid >> 5;
    if (tid == 0) sbase = 0;
    __syncthreads();
    for (int base = 0; base < NN; base += 1024) {
        int i = base + tid;
        int c = (i < NN) ? g_cnt[i] : 0;
        int v = c;
        #pragma unroll
        for (int o = 1; o < 32; o <<= 1) {
            int t = __shfl_up_sync(FULLMASK, v, o);
            if (lane >= o) v += t;
        }
        if (lane == 31) wsum[warp] = v;
        __syncthreads();
        if (warp == 0) {
            int w = wsum[lane];
            #pragma unroll
            for (int o = 1; o < 32; o <<= 1) {
                int t = __shfl_up_sync(FULLMASK, w, o);
                if (lane >= o) w += t;
            }
            wsum[lane] = w;
        }
        __syncthreads();
        int warpoff = warp ? wsum[warp - 1] : 0;
        int total = wsum[31];
        int excl = sbase + warpoff + v - c;
        if (i < NN) { g_off[i] = excl; g_cur[i] = excl; }
        __syncthreads();
        if (tid == 0) sbase += total;
        __syncthreads();
    }
    if (threadIdx.x == 0) g_off[NN] = sbase;
}

__global__ void sortedge_kernel(const int* __restrict__ ei, int E) {
    int j = blockIdx.x * blockDim.x + threadIdx.x;
    if (j >= E) return;
    int src = ei[j];
    int dst = ei[E + j];
    int pos = atomicAdd(&g_cur[dst], 1);
    if (pos < EMAX) g_srcs[pos] = src;
}

// ============================================================================
// K1: h = xp @ W  (+ attention scalars as_n, ad_n). Warp: NPW nodes x GROUPS.
// ============================================================================
template <int KDIM, int NPW, int GROUPS>
__global__ void gemm_attn_kernel(const float* __restrict__ xp,
                                 const float* __restrict__ W,
                                 const float* __restrict__ a_s,
                                 const float* __restrict__ a_d) {
    __shared__ float Ws[KDIM * 64];
    __shared__ float xs[8][NPW][KDIM];
    int tid = threadIdx.x;
    for (int i = tid; i < KDIM * 64; i += 256) Ws[i] = W[i];
    __syncthreads();

    int warp = tid >> 5, lane = tid & 31;
    const float* src = xp ? xp : g_h;
    float asl0 = a_s[lane], asl1 = a_s[lane + 32];
    float adl0 = a_d[lane], adl1 = a_d[lane + 32];

    for (int g = 0; g < GROUPS; g++) {
        int nbase = ((blockIdx.x * 8 + warp) * GROUPS + g) * NPW;
        if (nbase >= NN) break;
        #pragma unroll
        for (int j = 0; j < NPW; j++) {
            int n = nbase + j;
            if (n < NN) {
                #pragma unroll
                for (int k = lane; k < KDIM; k += 32)
                    xs[warp][j][k] = src[(size_t)n * KDIM + k];
            }
        }
        __syncwarp();

        float acc0[NPW], acc1[NPW];
        #pragma unroll
        for (int j = 0; j < NPW; j++) { acc0[j] = 0.f; acc1[j] = 0.f; }

        #pragma unroll 4
        for (int k = 0; k < KDIM; k++) {
            float w0 = Ws[k * 64 + lane];
            float w1 = Ws[k * 64 + lane + 32];
            #pragma unroll
            for (int j = 0; j < NPW; j++) {
                float xv = xs[warp][j][k];
                acc0[j] = fmaf(xv, w0, acc0[j]);
                acc1[j] = fmaf(xv, w1, acc1[j]);
            }
        }

        #pragma unroll
        for (int j = 0; j < NPW; j++) {
            int n = nbase + j;
            if (n >= NN) break;
            g_hn[(size_t)n * 64 + lane]      = acc0[j];
            g_hn[(size_t)n * 64 + lane + 32] = acc1[j];
            float s = acc0[j] * asl0 + acc1[j] * asl1;
            float d = acc0[j] * adl0 + acc1[j] * adl1;
            #pragma unroll
            for (int o = 16; o > 0; o >>= 1) {
                s += __shfl_xor_sync(FULLMASK, s, o);
                d += __shfl_xor_sync(FULLMASK, d, o);
            }
            if (lane == 0) { g_asn[n] = s; g_adn[n] = d; }
        }
        __syncwarp();
    }
}

// ============================================================================
// K2 (fused): per-dst gather-aggregate + softmax-normalize + bias/relu/BN
//             [+ proj residual] [+ mean-pool accum]. One warp per node.
// Lane l owns channels 2l and 2l+1 (float2 loads). Edge metadata (src index +
// softmax weight) is batched 32-wide per warp and distributed via shuffles so
// the only per-edge dependent load is the h-row gather itself (high MLP).
// ============================================================================
template <bool HAS_PROJ, bool DO_POOL>
__global__ void aggregate_kernel(const float* __restrict__ bias,
                                 const float* __restrict__ bng, const float* __restrict__ bnb,
                                 const float* __restrict__ bnm, const float* __restrict__ bnv,
                                 const float* __restrict__ projW, const float* __restrict__ projb) {
    __shared__ float Ws[HAS_PROJ ? 4096 : 64];
    __shared__ float bsum[64];
    int tid = threadIdx.x;
    if (HAS_PROJ)
        for (int i = tid; i < 4096; i += 256) Ws[i] = projW[i];
    if (DO_POOL && tid < 64) bsum[tid] = 0.f;
    __syncthreads();

    int warp = tid >> 5, lane = tid & 31;
    int c0 = lane * 2, c1 = c0 + 1;
    float b0 = bias[c0], b1 = bias[c1];
    float sc0 = bng[c0] * rsqrtf(bnv[c0] + 1e-5f);
    float sc1 = bng[c1] * rsqrtf(bnv[c1] + 1e-5f);
    float sh0 = bnb[c0] - bnm[c0] * sc0;
    float sh1 = bnb[c1] - bnm[c1] * sc1;
    float pb0 = HAS_PROJ ? projb[c0] : 0.f;
    float pb1 = HAS_PROJ ? projb[c1] : 0.f;

    #pragma unroll 1
    for (int g = 0; g < 8; g++) {
        int n = (blockIdx.x * 8 + warp) * 8 + g;
        if (n >= NN) break;
        int start = g_off[n], end = g_off[n + 1];
        float adn_n = g_adn[n];
        float wself = __expf(lrelu(g_asn[n] + adn_n));
        float2 hvs = *(const float2*)(g_hn + (size_t)n * 64 + c0);
        float accx = wself * hvs.x;
        float accy = wself * hvs.y;
        float denom = wself;

        for (int base = start; base < end; base += 32) {
            int m = end - base;                     // valid edges in this batch
            int cnt = m < 32 ? m : 32;
            int idx = (lane < m) ? __ldg(&g_srcs[base + lane]) : 0;
            float wl = (lane < m) ? __expf(lrelu(__ldg(&g_asn[idx]) + adn_n)) : 0.f;

            // denominator: warp-reduce the batch's weights once
            float ws = wl;
            #pragma unroll
            for (int o = 16; o > 0; o >>= 1)
                ws += __shfl_xor_sync(FULLMASK, ws, o);
            denom += ws;

            int e = 0;
            for (; e + 8 <= cnt; e += 8) {
                #pragma unroll
                for (int u = 0; u < 8; u++) {
                    int s = __shfl_sync(FULLMASK, idx, e + u);
                    float w = __shfl_sync(FULLMASK, wl, e + u);
                    float2 hv = *(const float2*)(g_hn + (size_t)s * 64 + c0);
                    accx = fmaf(w, hv.x, accx);
                    accy = fmaf(w, hv.y, accy);
                }
            }
            for (; e < cnt; e++) {
                int s = __shfl_sync(FULLMASK, idx, e);
                float w = __shfl_sync(FULLMASK, wl, e);
                float2 hv = *(const float2*)(g_hn + (size_t)s * 64 + c0);
                accx = fmaf(w, hv.x, accx);
                accy = fmaf(w, hv.y, accy);
            }
        }

        float inv = 1.f / (denom + 1e-16f);
        float o0 = accx * inv + b0;
        float o1 = accy * inv + b1;
        o0 = o0 > 0.f ? o0 : 0.f;
        o1 = o1 > 0.f ? o1 : 0.f;
        float y0 = o0 * sc0 + sh0;
        float y1 = o1 * sc1 + sh1;

        if (HAS_PROJ) {
            float2 xv2 = *(const float2*)(g_h + (size_t)n * 64 + c0);
            float px = pb0, py = pb1;
            #pragma unroll 8
            for (int kk = 0; kk < 32; kk++) {
                float xb0 = __shfl_sync(FULLMASK, xv2.x, kk);
                float xb1 = __shfl_sync(FULLMASK, xv2.y, kk);
                float2 w0 = *(const float2*)&Ws[(2 * kk) * 64 + c0];
                float2 w1 = *(const float2*)&Ws[(2 * kk + 1) * 64 + c0];
                px = fmaf(xb0, w0.x, px);
                px = fmaf(xb1, w1.x, px);
                py = fmaf(xb0, w0.y, py);
                py = fmaf(xb1, w1.y, py);
            }
            y0 += px; y1 += py;
        }

        g_h[(size_t)n * 64 + c0] = y0;
        g_h[(size_t)n * 64 + c1] = y1;
        if (DO_POOL) {
            atomicAdd(&bsum[c0], y0);
            atomicAdd(&bsum[c1], y1);
        }
    }
    if (DO_POOL) {
        __syncthreads();
        if (tid < 64) atomicAdd(&g_pool[tid * 32], bsum[tid]);
    }
}

// ============================================================================
// Head: g = pool/N; h1 = bn(relu(g@hW1+hb1)); out = h1@hW2 + hb2
// ============================================================================
__global__ void head_kernel(const float* __restrict__ hW1, const float* __restrict__ hb1,
                            const float* __restrict__ hg, const float* __restrict__ hbb,
                            const float* __restrict__ hm, const float* __restrict__ hv,
                            const float* __restrict__ hW2, const float* __restrict__ hb2,
                            float* __restrict__ out) {
    __shared__ float gsh[64];
    __shared__ float h1[32];
    int t = threadIdx.x;
    if (t < 64) gsh[t] = g_pool[t * 32] * (1.f / (float)NN);
    __syncthreads();
    if (t < 32) {
        float acc = hb1[t];
        #pragma unroll 8
        for (int k = 0; k < 64; k++) acc = fmaf(gsh[k], hW1[k * 32 + t], acc);
        acc = acc > 0.f ? acc : 0.f;
        float sc = hg[t] * rsqrtf(hv[t] + 1e-5f);
        h1[t] = (acc - hm[t]) * sc + hbb[t];
    }
    __syncthreads();
    if (t == 0) {
        float acc = hb2[0];
        #pragma unroll
        for (int j = 0; j < 32; j++) acc = fmaf(h1[j], hW2[j], acc);
        out[0] = acc;
    }
}

// ============================================================================
extern "C" void kernel_launch(void* const* d_in, const int* in_sizes, int n_in,
                              void* d_out, int out_size) {
    const float* x        = (const float*)d_in[0];
    const int*   ei       = (const int*)d_in[1];
    const float* conv1_W  = (const float*)d_in[2];
    const float* conv1_as = (const float*)d_in[3];
    const float* conv1_ad = (const float*)d_in[4];
    const float* conv1_b  = (const float*)d_in[5];
    const float* convW    = (const float*)d_in[6];
    const float* conv_as  = (const float*)d_in[7];
    const float* conv_ad  = (const float*)d_in[8];
    const float* conv_b   = (const float*)d_in[9];
    const float* bn_g     = (const float*)d_in[10];
    const float* bn_b     = (const float*)d_in[11];
    const float* bn_m     = (const float*)d_in[12];
    const float* bn_v     = (const float*)d_in[13];
    const float* projW    = (const float*)d_in[14];
    const float* projb    = (const float*)d_in[15];
    const float* hW1      = (const float*)d_in[16];
    const float* hb1      = (const float*)d_in[17];
    const float* hbn_g    = (const float*)d_in[18];
    const float* hbn_b    = (const float*)d_in[19];
    const float* hbn_m    = (const float*)d_in[20];
    const float* hbn_v    = (const float*)d_in[21];
    const float* hW2      = (const float*)d_in[22];
    const float* hb2      = (const float*)d_in[23];

    int E = in_sizes[1] / 2;

    const int edge_blocks = (E + 255) / 256;
    const int agg_blocks  = (NN + 63) / 64;    // 8 warps x 8 nodes
    const int g128_blocks = (NN + 127) / 128;  // NPW=2, GROUPS=8
    const int g64_blocks  = (NN + 127) / 128;  // NPW=8, GROUPS=2

    // ---- build CSR (edges identical for all layers) ----
    zero_kernel<<<(NN + 255) / 256, 256>>>();
    hist_kernel<<<edge_blocks, 256>>>(ei, E);
    scan_kernel<<<1, 1024>>>();
    sortedge_kernel<<<edge_blocks, 256>>>(ei, E);

    // ---- layer 1 (IN=128, no proj) ----
    gemm_attn_kernel<128, 2, 8><<<g128_blocks, 256>>>(x, conv1_W, conv1_as, conv1_ad);
    aggregate_kernel<false, false><<<agg_blocks, 256>>>(conv1_b, bn_g, bn_b, bn_m, bn_v,
                                                        nullptr, nullptr);

    // ---- layers 2..5 ----
    for (int l = 0; l < 4; l++) {
        gemm_attn_kernel<64, 8, 2><<<g64_blocks, 256>>>(nullptr, convW + l * 4096,
                                                        conv_as + l * 64, conv_ad + l * 64);
        if (l == 3)
            aggregate_kernel<true, true><<<agg_blocks, 256>>>(conv_b + l * 64,
                bn_g + (l + 1) * 64, bn_b + (l + 1) * 64, bn_m + (l + 1) * 64, bn_v + (l + 1) * 64,
                projW + l * 4096, projb + l * 64);
        else
            aggregate_kernel<true, false><<<agg_blocks, 256>>>(conv_b + l * 64,
                bn_g + (l + 1) * 64, bn_b + (l + 1) * 64, bn_m + (l + 1) * 64, bn_v + (l + 1) * 64,
                projW + l * 4096, projb + l * 64);
    }

    // ---- head ----
    head_kernel<<<1, 64>>>(hW1, hb1, hbn_g, hbn_b, hbn_m, hbn_v, hW2, hb2, (float*)d_out);
}

// round 4
// speedup vs baseline: 1.6172x; 1.3780x over previous
#include <cuda_runtime.h>
#include <cstddef>

#define NN 50000
#define HD 64
#define EMAX 800000
#define FULLMASK 0xffffffffu

// ---- scratch (device globals) ----
__device__ __align__(256) float g_h[NN * HD];     // xp (layer input / output)
__device__ __align__(256) float g_hn[NN * HD];    // h = xp @ W
__device__ __align__(256) float g_proj[NN * HD];  // xp @ projW + projb
__device__ float g_asn[NN];
__device__ float g_adn[NN];
__device__ float g_pool[64 * 32];                 // padded: channel c at c*32
__device__ int   g_cnt[NN];
__device__ int   g_off[NN + 1];
__device__ int   g_cur[NN];
__device__ int   g_srcs[EMAX];
__device__ int   g_dsts[EMAX];
__device__ float g_w[EMAX];

__device__ __forceinline__ float lrelu(float x) { return x > 0.f ? x : 0.2f * x; }

// ============================================================================
// CSR build (once per launch)
// ============================================================================
__global__ void zero_kernel() {
    int i = blockIdx.x * blockDim.x + threadIdx.x;
    if (i < NN) g_cnt[i] = 0;
    if (blockIdx.x == 0 && threadIdx.x < 64) g_pool[threadIdx.x * 32] = 0.f;
}

__global__ void hist_kernel(const int* __restrict__ ei, int E) {
    int j = blockIdx.x * blockDim.x + threadIdx.x;
    if (j >= E) return;
    atomicAdd(&g_cnt[ei[E + j]], 1);
}

__global__ void scan_kernel() {   // single block, 1024 threads
    __shared__ int wsum[32];
    __shared__ int sbase;
    int tid = threadIdx.x, lane = tid & 31, warp = tid >> 5;
    if (tid == 0) sbase = 0;
    __syncthreads();
    for (int base = 0; base < NN; base += 1024) {
        int i = base + tid;
        int c = (i < NN) ? g_cnt[i] : 0;
        int v = c;
        #pragma unroll
        for (int o = 1; o < 32; o <<= 1) {
            int t = __shfl_up_sync(FULLMASK, v, o);
            if (lane >= o) v += t;
        }
        if (lane == 31) wsum[warp] = v;
        __syncthreads();
        if (warp == 0) {
            int w = wsum[lane];
            #pragma unroll
            for (int o = 1; o < 32; o <<= 1) {
                int t = __shfl_up_sync(FULLMASK, w, o);
                if (lane >= o) w += t;
            }
            wsum[lane] = w;
        }
        __syncthreads();
        int warpoff = warp ? wsum[warp - 1] : 0;
        int total = wsum[31];
        int excl = sbase + warpoff + v - c;
        if (i < NN) { g_off[i] = excl; g_cur[i] = excl; }
        __syncthreads();
        if (tid == 0) sbase += total;
        __syncthreads();
    }
    if (threadIdx.x == 0) g_off[NN] = sbase;
}

__global__ void sortedge_kernel(const int* __restrict__ ei, int E) {
    int j = blockIdx.x * blockDim.x + threadIdx.x;
    if (j >= E) return;
    int src = ei[j];
    int dst = ei[E + j];
    int pos = atomicAdd(&g_cur[dst], 1);
    if (pos < EMAX) { g_srcs[pos] = src; g_dsts[pos] = dst; }
}

// ============================================================================
// K1: h = xp @ W (+ attention scalars) [+ fused proj residual GEMM].
// ============================================================================
template <int KDIM, int NPW, int GROUPS, bool HAS_PROJ>
__global__ void gemm_attn_kernel(const float* __restrict__ xp,
                                 const float* __restrict__ W,
                                 const float* __restrict__ a_s,
                                 const float* __restrict__ a_d,
                                 const float* __restrict__ projW,
                                 const float* __restrict__ projb) {
    __shared__ float Ws[KDIM * 64];
    __shared__ float Ps[HAS_PROJ ? KDIM * 64 : 1];
    __shared__ float xs[8][NPW][KDIM];
    int tid = threadIdx.x;
    for (int i = tid; i < KDIM * 64; i += 256) Ws[i] = W[i];
    if (HAS_PROJ)
        for (int i = tid; i < KDIM * 64; i += 256) Ps[i] = projW[i];
    __syncthreads();

    int warp = tid >> 5, lane = tid & 31;
    const float* src = xp ? xp : g_h;
    float asl0 = a_s[lane], asl1 = a_s[lane + 32];
    float adl0 = a_d[lane], adl1 = a_d[lane + 32];
    float pb0 = HAS_PROJ ? projb[lane] : 0.f;
    float pb1 = HAS_PROJ ? projb[lane + 32] : 0.f;

    for (int g = 0; g < GROUPS; g++) {
        int nbase = ((blockIdx.x * 8 + warp) * GROUPS + g) * NPW;
        if (nbase >= NN) break;
        #pragma unroll
        for (int j = 0; j < NPW; j++) {
            int n = nbase + j;
            if (n < NN) {
                #pragma unroll
                for (int k = lane; k < KDIM; k += 32)
                    xs[warp][j][k] = src[(size_t)n * KDIM + k];
            }
        }
        __syncwarp();

        float acc0[NPW], acc1[NPW], pc0[NPW], pc1[NPW];
        #pragma unroll
        for (int j = 0; j < NPW; j++) {
            acc0[j] = 0.f; acc1[j] = 0.f;
            if (HAS_PROJ) { pc0[j] = 0.f; pc1[j] = 0.f; }
        }

        #pragma unroll 2
        for (int k = 0; k < KDIM; k++) {
            float w0 = Ws[k * 64 + lane];
            float w1 = Ws[k * 64 + lane + 32];
            float q0 = HAS_PROJ ? Ps[k * 64 + lane] : 0.f;
            float q1 = HAS_PROJ ? Ps[k * 64 + lane + 32] : 0.f;
            #pragma unroll
            for (int j = 0; j < NPW; j++) {
                float xv = xs[warp][j][k];
                acc0[j] = fmaf(xv, w0, acc0[j]);
                acc1[j] = fmaf(xv, w1, acc1[j]);
                if (HAS_PROJ) {
                    pc0[j] = fmaf(xv, q0, pc0[j]);
                    pc1[j] = fmaf(xv, q1, pc1[j]);
                }
            }
        }

        #pragma unroll
        for (int j = 0; j < NPW; j++) {
            int n = nbase + j;
            if (n >= NN) break;
            g_hn[(size_t)n * 64 + lane]      = acc0[j];
            g_hn[(size_t)n * 64 + lane + 32] = acc1[j];
            if (HAS_PROJ) {
                g_proj[(size_t)n * 64 + lane]      = pc0[j] + pb0;
                g_proj[(size_t)n * 64 + lane + 32] = pc1[j] + pb1;
            }
            float s = acc0[j] * asl0 + acc1[j] * asl1;
            float d = acc0[j] * adl0 + acc1[j] * adl1;
            #pragma unroll
            for (int o = 16; o > 0; o >>= 1) {
                s += __shfl_xor_sync(FULLMASK, s, o);
                d += __shfl_xor_sync(FULLMASK, d, o);
            }
            if (lane == 0) { g_asn[n] = s; g_adn[n] = d; }
        }
        __syncwarp();
    }
}

// ============================================================================
// K2: flat per-edge weight precompute (sorted order, latency-tolerant)
// ============================================================================
__global__ void edgew_kernel(int E) {
    int p = blockIdx.x * blockDim.x + threadIdx.x;
    if (p >= E) return;
    int s = g_srcs[p], d = g_dsts[p];
    g_w[p] = __expf(lrelu(g_asn[s] + g_adn[d]));
}

// ============================================================================
// K3: aggregate — ONE node per warp. Coalesced (src,w) batches via shuffles;
// the only per-edge global access is the coalesced 256B h-row gather.
// Epilogue: softmax-normalize + bias/relu/BN [+ proj add] [+ pool].
// ============================================================================
template <bool HAS_PROJ, bool DO_POOL>
__global__ void aggregate_kernel(const float* __restrict__ bias,
                                 const float* __restrict__ bng, const float* __restrict__ bnb,
                                 const float* __restrict__ bnm, const float* __restrict__ bnv) {
    __shared__ float bsum[64];
    int tid = threadIdx.x;
    if (DO_POOL) {
        if (tid < 64) bsum[tid] = 0.f;
        __syncthreads();
    }

    int warp = tid >> 5, lane = tid & 31;
    int n = blockIdx.x * 8 + warp;
    if (n < NN) {
        int c0 = lane * 2, c1 = c0 + 1;
        int start = g_off[n], end = g_off[n + 1];
        float adn_n = g_adn[n];
        float wself = __expf(lrelu(g_asn[n] + adn_n));
        float2 hvs = *(const float2*)(g_hn + (size_t)n * 64 + c0);
        float accx = wself * hvs.x;
        float accy = wself * hvs.y;
        float denom = wself;

        for (int base = start; base < end; base += 32) {
            int m = end - base;
            int cnt = m < 32 ? m : 32;
            int idx  = (lane < m) ? __ldg(&g_srcs[base + lane]) : 0;
            float wv = (lane < m) ? __ldg(&g_w[base + lane]) : 0.f;

            float ws = wv;
            #pragma unroll
            for (int o = 16; o > 0; o >>= 1)
                ws += __shfl_xor_sync(FULLMASK, ws, o);
            denom += ws;

            int e = 0;
            for (; e + 8 <= cnt; e += 8) {
                #pragma unroll
                for (int u = 0; u < 8; u++) {
                    int s  = __shfl_sync(FULLMASK, idx, e + u);
                    float w = __shfl_sync(FULLMASK, wv, e + u);
                    float2 hv = *(const float2*)(g_hn + (size_t)s * 64 + c0);
                    accx = fmaf(w, hv.x, accx);
                    accy = fmaf(w, hv.y, accy);
                }
            }
            for (; e < cnt; e++) {
                int s  = __shfl_sync(FULLMASK, idx, e);
                float w = __shfl_sync(FULLMASK, wv, e);
                float2 hv = *(const float2*)(g_hn + (size_t)s * 64 + c0);
                accx = fmaf(w, hv.x, accx);
                accy = fmaf(w, hv.y, accy);
            }
        }

        float sc0 = bng[c0] * rsqrtf(bnv[c0] + 1e-5f);
        float sc1 = bng[c1] * rsqrtf(bnv[c1] + 1e-5f);
        float sh0 = bnb[c0] - bnm[c0] * sc0;
        float sh1 = bnb[c1] - bnm[c1] * sc1;

        float inv = 1.f / (denom + 1e-16f);
        float o0 = accx * inv + bias[c0];
        float o1 = accy * inv + bias[c1];
        o0 = o0 > 0.f ? o0 : 0.f;
        o1 = o1 > 0.f ? o1 : 0.f;
        float y0 = o0 * sc0 + sh0;
        float y1 = o1 * sc1 + sh1;

        if (HAS_PROJ) {
            float2 pv = *(const float2*)(g_proj + (size_t)n * 64 + c0);
            y0 += pv.x; y1 += pv.y;
        }

        g_h[(size_t)n * 64 + c0] = y0;
        g_h[(size_t)n * 64 + c1] = y1;
        if (DO_POOL) {
            atomicAdd(&bsum[c0], y0);
            atomicAdd(&bsum[c1], y1);
        }
    }
    if (DO_POOL) {
        __syncthreads();
        if (tid < 64) atomicAdd(&g_pool[tid * 32], bsum[tid]);
    }
}

// ============================================================================
// Head
// ============================================================================
__global__ void head_kernel(const float* __restrict__ hW1, const float* __restrict__ hb1,
                            const float* __restrict__ hg, const float* __restrict__ hbb,
                            const float* __restrict__ hm, const float* __restrict__ hv,
                            const float* __restrict__ hW2, const float* __restrict__ hb2,
                            float* __restrict__ out) {
    __shared__ float gsh[64];
    __shared__ float h1[32];
    int t = threadIdx.x;
    if (t < 64) gsh[t] = g_pool[t * 32] * (1.f / (float)NN);
    __syncthreads();
    if (t < 32) {
        float acc = hb1[t];
        #pragma unroll 8
        for (int k = 0; k < 64; k++) acc = fmaf(gsh[k], hW1[k * 32 + t], acc);
        acc = acc > 0.f ? acc : 0.f;
        float sc = hg[t] * rsqrtf(hv[t] + 1e-5f);
        h1[t] = (acc - hm[t]) * sc + hbb[t];
    }
    __syncthreads();
    if (t == 0) {
        float acc = hb2[0];
        #pragma unroll
        for (int j = 0; j < 32; j++) acc = fmaf(h1[j], hW2[j], acc);
        out[0] = acc;
    }
}

// ============================================================================
extern "C" void kernel_launch(void* const* d_in, const int* in_sizes, int n_in,
                              void* d_out, int out_size) {
    const float* x        = (const float*)d_in[0];
    const int*   ei       = (const int*)d_in[1];
    const float* conv1_W  = (const float*)d_in[2];
    const float* conv1_as = (const float*)d_in[3];
    const float* conv1_ad = (const float*)d_in[4];
    const float* conv1_b  = (const float*)d_in[5];
    const float* convW    = (const float*)d_in[6];
    const float* conv_as  = (const float*)d_in[7];
    const float* conv_ad  = (const float*)d_in[8];
    const float* conv_b   = (const float*)d_in[9];
    const float* bn_g     = (const float*)d_in[10];
    const float* bn_b     = (const float*)d_in[11];
    const float* bn_m     = (const float*)d_in[12];
    const float* bn_v     = (const float*)d_in[13];
    const float* projW    = (const float*)d_in[14];
    const float* projb    = (const float*)d_in[15];
    const float* hW1      = (const float*)d_in[16];
    const float* hb1      = (const float*)d_in[17];
    const float* hbn_g    = (const float*)d_in[18];
    const float* hbn_b    = (const float*)d_in[19];
    const float* hbn_m    = (const float*)d_in[20];
    const float* hbn_v    = (const float*)d_in[21];
    const float* hW2      = (const float*)d_in[22];
    const float* hb2      = (const float*)d_in[23];

    int E = in_sizes[1] / 2;

    const int edge_blocks = (E + 255) / 256;
    const int agg_blocks  = (NN + 7) / 8;      // ONE node per warp
    const int g128_blocks = (NN + 127) / 128;  // NPW=2, GROUPS=8
    const int g64_blocks  = (NN + 127) / 128;  // NPW=8, GROUPS=2

    // ---- build CSR ----
    zero_kernel<<<(NN + 255) / 256, 256>>>();
    hist_kernel<<<edge_blocks, 256>>>(ei, E);
    scan_kernel<<<1, 1024>>>();
    sortedge_kernel<<<edge_blocks, 256>>>(ei, E);

    // ---- layer 1 (IN=128, no proj) ----
    gemm_attn_kernel<128, 2, 8, false><<<g128_blocks, 256>>>(x, conv1_W, conv1_as, conv1_ad,
                                                             nullptr, nullptr);
    edgew_kernel<<<edge_blocks, 256>>>(E);
    aggregate_kernel<false, false><<<agg_blocks, 256>>>(conv1_b, bn_g, bn_b, bn_m, bn_v);

    // ---- layers 2..5 (fused proj GEMM) ----
    for (int l = 0; l < 4; l++) {
        gemm_attn_kernel<64, 8, 2, true><<<g64_blocks, 256>>>(nullptr, convW + l * 4096,
                                                              conv_as + l * 64, conv_ad + l * 64,
                                                              projW + l * 4096, projb + l * 64);
        edgew_kernel<<<edge_blocks, 256>>>(E);
        if (l == 3)
            aggregate_kernel<true, true><<<agg_blocks, 256>>>(conv_b + l * 64,
                bn_g + (l + 1) * 64, bn_b + (l + 1) * 64, bn_m + (l + 1) * 64, bn_v + (l + 1) * 64);
        else
            aggregate_kernel<true, false><<<agg_blocks, 256>>>(conv_b + l * 64,
                bn_g + (l + 1) * 64, bn_b + (l + 1) * 64, bn_m + (l + 1) * 64, bn_v + (l + 1) * 64);
    }

    // ---- head ----
    head_kernel<<<1, 64>>>(hW1, hb1, hbn_g, hbn_b, hbn_m, hbn_v, hW2, hb2, (float*)d_out);
}